// round 3
// baseline (speedup 1.0000x reference)
#include <cuda_runtime.h>

#define BATCH 4
#define NCTX 4096
#define DM 1024
#define DH 64
#define NT (BATCH * NCTX)

// Scratch (device globals — no allocations allowed)
__device__ float g_Q[NT * DH];
__device__ float g_K[NT * DH];
__device__ float g_V[NT * DH];
__device__ float g_Oh[NT * DH];

// ---------------------------------------------------------------------------
// Kernel A: QKV projection.  out[t,h] = sum_d x[t,d] * W[h,d] + b[h]
// M=16384, N=64, K=1024.  BM=128, BN=64, BK=16. 256 threads, 8x4 per thread.
// blockIdx.y selects Q / K / V.
// ---------------------------------------------------------------------------
__global__ __launch_bounds__(256, 1) void qkv_kernel(
    const float* __restrict__ x,
    const float* __restrict__ Wq, const float* __restrict__ bq,
    const float* __restrict__ Wk, const float* __restrict__ bk,
    const float* __restrict__ Wv, const float* __restrict__ bv)
{
    const float* W;
    const float* bias;
    float* out;
    if (blockIdx.y == 0)      { W = Wq; bias = bq; out = g_Q; }
    else if (blockIdx.y == 1) { W = Wk; bias = bk; out = g_K; }
    else                      { W = Wv; bias = bv; out = g_V; }

    __shared__ float Xs[16][132];  // [k][token]  (transposed), pitch mult of 4
    __shared__ float Ws[16][68];   // [k][h]      (transposed)

    const int t0  = blockIdx.x * 128;
    const int tid = threadIdx.x;
    const int tx  = tid & 15;   // 0..15  -> 4 output cols each
    const int ty  = tid >> 4;   // 0..15  -> 8 output rows each

    float acc[8][4];
#pragma unroll
    for (int i = 0; i < 8; i++)
#pragma unroll
        for (int j = 0; j < 4; j++) acc[i][j] = 0.0f;

    for (int k0 = 0; k0 < DM; k0 += 16) {
        __syncthreads();
        // load X tile 128x16 (transpose into smem)
#pragma unroll
        for (int s = 0; s < 2; s++) {
            int idx = tid * 2 + s;          // 0..511
            int row = idx >> 2;             // 0..127
            int c4  = idx & 3;              // 0..3
            float4 v = *(const float4*)&x[(t0 + row) * DM + k0 + c4 * 4];
            Xs[c4 * 4 + 0][row] = v.x;
            Xs[c4 * 4 + 1][row] = v.y;
            Xs[c4 * 4 + 2][row] = v.z;
            Xs[c4 * 4 + 3][row] = v.w;
        }
        // load W tile 64x16 (transpose)
        {
            int h  = tid >> 2;              // 0..63
            int c4 = tid & 3;
            float4 v = *(const float4*)&W[h * DM + k0 + c4 * 4];
            Ws[c4 * 4 + 0][h] = v.x;
            Ws[c4 * 4 + 1][h] = v.y;
            Ws[c4 * 4 + 2][h] = v.z;
            Ws[c4 * 4 + 3][h] = v.w;
        }
        __syncthreads();

#pragma unroll
        for (int k = 0; k < 16; k++) {
            float a[8], b[4];
            *(float4*)&a[0] = *(float4*)&Xs[k][ty * 8];
            *(float4*)&a[4] = *(float4*)&Xs[k][ty * 8 + 4];
            *(float4*)&b[0] = *(float4*)&Ws[k][tx * 4];
#pragma unroll
            for (int i = 0; i < 8; i++)
#pragma unroll
                for (int j = 0; j < 4; j++) acc[i][j] += a[i] * b[j];
        }
    }

    float4 b4 = *(const float4*)&bias[tx * 4];
#pragma unroll
    for (int i = 0; i < 8; i++) {
        float4 r = make_float4(acc[i][0] + b4.x, acc[i][1] + b4.y,
                               acc[i][2] + b4.z, acc[i][3] + b4.w);
        *(float4*)&out[(t0 + ty * 8 + i) * DH + tx * 4] = r;
    }
}

// ---------------------------------------------------------------------------
// Kernel B: causal flash attention, BM=BN=64, DH=64.
// 256 threads: 16x16 grid, thread owns 4x4 S-tile and 4x4 O-tile.
// smem: Qs [h][i] transposed, KsPt aliased (K transposed [h][j], then P [j][i]),
// Vs [j][h].  Pitch 64 -> exactly 48KB static smem.
// ---------------------------------------------------------------------------
__global__ __launch_bounds__(256, 1) void attn_kernel()
{
    __shared__ float Qs[64 * 64];   // Qs[h*64 + i]
    __shared__ float KsPt[64 * 64]; // K: [h*64 + j];  later  P: [j*64 + i]
    __shared__ float Vs[64 * 64];   // Vs[j*64 + h]

    const int b   = blockIdx.y;
    const int qt  = gridDim.x - 1 - blockIdx.x;   // heavy tiles first
    const int q0  = qt * 64;
    const int tid = threadIdx.x;
    const int tx  = tid & 15;
    const int ty  = tid >> 4;

    // load Q tile, transposed
    const float* Qg = g_Q + ((size_t)b * NCTX + q0) * DH;
#pragma unroll
    for (int s = 0; s < 4; s++) {
        int idx = tid + s * 256;   // 0..1023
        int row = idx >> 4;        // 0..63
        int c4  = idx & 15;
        float4 v = *(const float4*)&Qg[row * DH + c4 * 4];
        Qs[(c4 * 4 + 0) * 64 + row] = v.x;
        Qs[(c4 * 4 + 1) * 64 + row] = v.y;
        Qs[(c4 * 4 + 2) * 64 + row] = v.z;
        Qs[(c4 * 4 + 3) * 64 + row] = v.w;
    }

    float o[4][4];
    float mrun[4], lrun[4];
#pragma unroll
    for (int i = 0; i < 4; i++) {
        mrun[i] = -1e30f;
        lrun[i] = 0.0f;
#pragma unroll
        for (int j = 0; j < 4; j++) o[i][j] = 0.0f;
    }

    const float scale = 0.03125f;  // 1/sqrt(1024)

    for (int kt = 0; kt <= qt; kt++) {
        const int k0 = kt * 64;
        __syncthreads();  // prev PV done before overwriting K/V/P buffers
        const float* Kg = g_K + ((size_t)b * NCTX + k0) * DH;
        const float* Vg = g_V + ((size_t)b * NCTX + k0) * DH;
#pragma unroll
        for (int s = 0; s < 4; s++) {
            int idx = tid + s * 256;
            int row = idx >> 4;
            int c4  = idx & 15;
            float4 kv = *(const float4*)&Kg[row * DH + c4 * 4];
            KsPt[(c4 * 4 + 0) * 64 + row] = kv.x;
            KsPt[(c4 * 4 + 1) * 64 + row] = kv.y;
            KsPt[(c4 * 4 + 2) * 64 + row] = kv.z;
            KsPt[(c4 * 4 + 3) * 64 + row] = kv.w;
            float4 vv = *(const float4*)&Vg[row * DH + c4 * 4];
            *(float4*)&Vs[row * 64 + c4 * 4] = vv;
        }
        __syncthreads();

        // S = Q K^T
        float s4[4][4];
#pragma unroll
        for (int i = 0; i < 4; i++)
#pragma unroll
            for (int j = 0; j < 4; j++) s4[i][j] = 0.0f;

#pragma unroll 8
        for (int h = 0; h < 64; h++) {
            float4 q4 = *(float4*)&Qs[h * 64 + ty * 4];
            float4 k4 = *(float4*)&KsPt[h * 64 + tx * 4];
            float qa[4] = {q4.x, q4.y, q4.z, q4.w};
            float kb[4] = {k4.x, k4.y, k4.z, k4.w};
#pragma unroll
            for (int i = 0; i < 4; i++)
#pragma unroll
                for (int j = 0; j < 4; j++) s4[i][j] += qa[i] * kb[j];
        }

        // scale + causal mask
#pragma unroll
        for (int i = 0; i < 4; i++)
#pragma unroll
            for (int j = 0; j < 4; j++) {
                float v = s4[i][j] * scale;
                if (kt == qt && (tx * 4 + j) > (ty * 4 + i)) v = -1e30f;
                s4[i][j] = v;
            }

        // online softmax (row stats via half-warp shuffles over tx)
#pragma unroll
        for (int i = 0; i < 4; i++) {
            float tmax = fmaxf(fmaxf(s4[i][0], s4[i][1]), fmaxf(s4[i][2], s4[i][3]));
#pragma unroll
            for (int m = 8; m >= 1; m >>= 1)
                tmax = fmaxf(tmax, __shfl_xor_sync(0xffffffffu, tmax, m));
            float mnew  = fmaxf(mrun[i], tmax);
            float alpha = __expf(mrun[i] - mnew);
            float psum  = 0.0f;
#pragma unroll
            for (int j = 0; j < 4; j++) {
                float p = __expf(s4[i][j] - mnew);
                s4[i][j] = p;
                psum += p;
            }
#pragma unroll
            for (int m = 8; m >= 1; m >>= 1)
                psum += __shfl_xor_sync(0xffffffffu, psum, m);
            lrun[i] = lrun[i] * alpha + psum;
            mrun[i] = mnew;
#pragma unroll
            for (int h = 0; h < 4; h++) o[i][h] *= alpha;
        }

        __syncthreads();  // all S-reads of KsPt done before P overwrites it
        // write P transposed: P[j][i]
#pragma unroll
        for (int j = 0; j < 4; j++)
            *(float4*)&KsPt[(tx * 4 + j) * 64 + ty * 4] =
                make_float4(s4[0][j], s4[1][j], s4[2][j], s4[3][j]);
        __syncthreads();

        // O += P V
#pragma unroll 8
        for (int j = 0; j < 64; j++) {
            float4 p4 = *(float4*)&KsPt[j * 64 + ty * 4];
            float4 v4 = *(float4*)&Vs[j * 64 + tx * 4];
            float pa[4] = {p4.x, p4.y, p4.z, p4.w};
            float vb[4] = {v4.x, v4.y, v4.z, v4.w};
#pragma unroll
            for (int i = 0; i < 4; i++)
#pragma unroll
                for (int h = 0; h < 4; h++) o[i][h] += pa[i] * vb[h];
        }
    }

    // normalize + store
#pragma unroll
    for (int i = 0; i < 4; i++) {
        float inv = 1.0f / lrun[i];
        float4 r = make_float4(o[i][0] * inv, o[i][1] * inv,
                               o[i][2] * inv, o[i][3] * inv);
        *(float4*)&g_Oh[((size_t)b * NCTX + q0 + ty * 4 + i) * DH + tx * 4] = r;
    }
}

// ---------------------------------------------------------------------------
// Kernel C: output projection.  out[t,d] = sum_h Oh[t,h] * Wo[d,h] + bo[d]
// M=16384, N=1024, K=64.  BM=BN=64, one K pass.
// ---------------------------------------------------------------------------
__global__ __launch_bounds__(256, 1) void proj_kernel(
    const float* __restrict__ Wo, const float* __restrict__ bo,
    float* __restrict__ out)
{
    __shared__ float Ohs[64 * 68];  // [h][t]  transposed
    __shared__ float Wos[64 * 68];  // [h][d]  transposed

    const int t0  = blockIdx.x * 64;
    const int d0  = blockIdx.y * 64;
    const int tid = threadIdx.x;
    const int tx  = tid & 15;
    const int ty  = tid >> 4;

#pragma unroll
    for (int s = 0; s < 4; s++) {
        int idx = tid + s * 256;
        int row = idx >> 4;
        int c4  = idx & 15;
        float4 v = *(const float4*)&g_Oh[(t0 + row) * DH + c4 * 4];
        Ohs[(c4 * 4 + 0) * 68 + row] = v.x;
        Ohs[(c4 * 4 + 1) * 68 + row] = v.y;
        Ohs[(c4 * 4 + 2) * 68 + row] = v.z;
        Ohs[(c4 * 4 + 3) * 68 + row] = v.w;
        float4 w = *(const float4*)&Wo[(d0 + row) * DH + c4 * 4];
        Wos[(c4 * 4 + 0) * 68 + row] = w.x;
        Wos[(c4 * 4 + 1) * 68 + row] = w.y;
        Wos[(c4 * 4 + 2) * 68 + row] = w.z;
        Wos[(c4 * 4 + 3) * 68 + row] = w.w;
    }
    __syncthreads();

    float acc[4][4];
#pragma unroll
    for (int i = 0; i < 4; i++)
#pragma unroll
        for (int j = 0; j < 4; j++) acc[i][j] = 0.0f;

#pragma unroll 8
    for (int h = 0; h < 64; h++) {
        float4 o4 = *(float4*)&Ohs[h * 68 + ty * 4];
        float4 w4 = *(float4*)&Wos[h * 68 + tx * 4];
        float oa[4] = {o4.x, o4.y, o4.z, o4.w};
        float wb[4] = {w4.x, w4.y, w4.z, w4.w};
#pragma unroll
        for (int i = 0; i < 4; i++)
#pragma unroll
            for (int j = 0; j < 4; j++) acc[i][j] += oa[i] * wb[j];
    }

    float4 b4 = *(const float4*)&bo[d0 + tx * 4];
#pragma unroll
    for (int i = 0; i < 4; i++) {
        float4 r = make_float4(acc[i][0] + b4.x, acc[i][1] + b4.y,
                               acc[i][2] + b4.z, acc[i][3] + b4.w);
        *(float4*)&out[(size_t)(t0 + ty * 4 + i) * DM + d0 + tx * 4] = r;
    }
}

// ---------------------------------------------------------------------------
extern "C" void kernel_launch(void* const* d_in, const int* in_sizes, int n_in,
                              void* d_out, int out_size)
{
    const float* x   = (const float*)d_in[0];
    const float* Wq  = (const float*)d_in[1];
    const float* bq  = (const float*)d_in[2];
    const float* Wk  = (const float*)d_in[3];
    const float* bk  = (const float*)d_in[4];
    const float* Wov = (const float*)d_in[5];
    const float* bov = (const float*)d_in[6];
    const float* Wo  = (const float*)d_in[7];
    const float* bo  = (const float*)d_in[8];
    float* out = (float*)d_out;

    qkv_kernel<<<dim3(NT / 128, 3), 256>>>(x, Wq, bq, Wk, bk, Wov, bov);
    attn_kernel<<<dim3(NCTX / 64, BATCH), 256>>>();
    proj_kernel<<<dim3(NT / 64, DM / 64), 256>>>(Wo, bo, out);
}

// round 5
// speedup vs baseline: 2.0309x; 2.0309x over previous
#include <cuda_runtime.h>

#define BATCH 4
#define NCTX 4096
#define DM 1024
#define DH 64
#define NT (BATCH * NCTX)

typedef unsigned long long u64;

__device__ float g_Q[NT * DH];
__device__ float g_K[NT * DH];
__device__ float g_V[NT * DH];
__device__ float g_Oh[NT * DH];

// packed fp32x2 helpers (FFMA2 path — ptxas won't emit it, inline PTX does)
__device__ __forceinline__ u64 pk2(float x) {
    u64 r; asm("mov.b64 %0, {%1, %1};" : "=l"(r) : "f"(x)); return r;
}
__device__ __forceinline__ void fma2(u64& d, u64 a, u64 b) {
    asm("fma.rn.f32x2 %0, %1, %2, %0;" : "+l"(d) : "l"(a), "l"(b));
}
__device__ __forceinline__ u64 mul2(u64 a, u64 b) {
    u64 r; asm("mul.rn.f32x2 %0, %1, %2;" : "=l"(r) : "l"(a), "l"(b)); return r;
}
__device__ __forceinline__ float2 up2(u64 p) {
    float2 v; asm("mov.b64 {%0, %1}, %2;" : "=f"(v.x), "=f"(v.y) : "l"(p)); return v;
}

// ---------------------------------------------------------------------------
// Kernel A: QKV projection. out[t,h] = sum_d x[t,d]*W[h,d] + b[h]
// BM=128, BN=64, BK=16, 256 threads, 8x4/thread, FFMA2 pairs along h.
// ---------------------------------------------------------------------------
__global__ __launch_bounds__(256, 1) void qkv_kernel(
    const float* __restrict__ x,
    const float* __restrict__ Wq, const float* __restrict__ bq,
    const float* __restrict__ Wk, const float* __restrict__ bk,
    const float* __restrict__ Wv, const float* __restrict__ bv)
{
    const float* W; const float* bias; float* out;
    if (blockIdx.y == 0)      { W = Wq; bias = bq; out = g_Q; }
    else if (blockIdx.y == 1) { W = Wk; bias = bk; out = g_K; }
    else                      { W = Wv; bias = bv; out = g_V; }

    __shared__ float Xs[16][132];  // [k][token]
    __shared__ float Ws[16][68];   // [k][h]

    const int t0  = blockIdx.x * 128;
    const int tid = threadIdx.x;
    const int tx  = tid & 15;   // 4 cols
    const int ty  = tid >> 4;   // 8 rows

    u64 acc2[8][2];
#pragma unroll
    for (int i = 0; i < 8; i++) { acc2[i][0] = 0ull; acc2[i][1] = 0ull; }

    for (int k0 = 0; k0 < DM; k0 += 16) {
        __syncthreads();
#pragma unroll
        for (int s = 0; s < 2; s++) {
            int idx = tid * 2 + s;
            int row = idx >> 2, c4 = idx & 3;
            float4 v = *(const float4*)&x[(size_t)(t0 + row) * DM + k0 + c4 * 4];
            Xs[c4 * 4 + 0][row] = v.x; Xs[c4 * 4 + 1][row] = v.y;
            Xs[c4 * 4 + 2][row] = v.z; Xs[c4 * 4 + 3][row] = v.w;
        }
        {
            int h = tid >> 2, c4 = tid & 3;
            float4 v = *(const float4*)&W[(size_t)h * DM + k0 + c4 * 4];
            Ws[c4 * 4 + 0][h] = v.x; Ws[c4 * 4 + 1][h] = v.y;
            Ws[c4 * 4 + 2][h] = v.z; Ws[c4 * 4 + 3][h] = v.w;
        }
        __syncthreads();

#pragma unroll
        for (int k = 0; k < 16; k++) {
            float a[8];
            *(float4*)&a[0] = *(const float4*)&Xs[k][ty * 8];
            *(float4*)&a[4] = *(const float4*)&Xs[k][ty * 8 + 4];
            ulonglong2 bp = *(const ulonglong2*)&Ws[k][tx * 4];
#pragma unroll
            for (int i = 0; i < 8; i++) {
                u64 pa = pk2(a[i]);
                fma2(acc2[i][0], pa, bp.x);
                fma2(acc2[i][1], pa, bp.y);
            }
        }
    }

    float4 b4 = *(const float4*)&bias[tx * 4];
#pragma unroll
    for (int i = 0; i < 8; i++) {
        float2 lo = up2(acc2[i][0]), hi = up2(acc2[i][1]);
        float4 r = make_float4(lo.x + b4.x, lo.y + b4.y, hi.x + b4.z, hi.y + b4.w);
        *(float4*)&out[(size_t)(t0 + ty * 8 + i) * DH + tx * 4] = r;
    }
}

// ---------------------------------------------------------------------------
// Kernel B: causal flash attention. BM=BN=64, 256 threads, 4x4/thread.
// FFMA2: S pairs along j (K cols), O pairs along h (V cols).
// 1D grid, snake rank so each SM's two CTAs sum to ~constant work.
// ---------------------------------------------------------------------------
__global__ __launch_bounds__(256, 1) void attn_kernel()
{
    __shared__ float Qs[64 * 64];   // [h][i], pre-scaled
    __shared__ float KsPt[64 * 64]; // K: [h][j]; later P: [j][i]
    __shared__ float Vs[64 * 64];   // [j][h]

    const int bid  = blockIdx.x;
    const int rank = (bid < 128) ? bid : 383 - bid;
    const int qt   = 63 - (rank >> 2);
    const int b    = rank & 3;
    const int q0   = qt * 64;
    const int tid  = threadIdx.x;
    const int tx   = tid & 15;
    const int ty   = tid >> 4;
    const float scale = 0.03125f;  // 1/sqrt(1024)

    const float* Qg = g_Q + ((size_t)b * NCTX + q0) * DH;
#pragma unroll
    for (int s = 0; s < 4; s++) {
        int idx = tid + s * 256;
        int row = idx >> 4, c4 = idx & 15;
        float4 v = *(const float4*)&Qg[row * DH + c4 * 4];
        Qs[(c4 * 4 + 0) * 64 + row] = v.x * scale;
        Qs[(c4 * 4 + 1) * 64 + row] = v.y * scale;
        Qs[(c4 * 4 + 2) * 64 + row] = v.z * scale;
        Qs[(c4 * 4 + 3) * 64 + row] = v.w * scale;
    }

    u64 o2[4][2];
    float mrun[4], lrun[4];
#pragma unroll
    for (int i = 0; i < 4; i++) {
        mrun[i] = -1e30f; lrun[i] = 0.0f;
        o2[i][0] = 0ull; o2[i][1] = 0ull;
    }

    for (int kt = 0; kt <= qt; kt++) {
        const int k0 = kt * 64;
        __syncthreads();
        const float* Kg = g_K + ((size_t)b * NCTX + k0) * DH;
        const float* Vg = g_V + ((size_t)b * NCTX + k0) * DH;
#pragma unroll
        for (int s = 0; s < 4; s++) {
            int idx = tid + s * 256;
            int row = idx >> 4, c4 = idx & 15;
            float4 kv = *(const float4*)&Kg[row * DH + c4 * 4];
            KsPt[(c4 * 4 + 0) * 64 + row] = kv.x;
            KsPt[(c4 * 4 + 1) * 64 + row] = kv.y;
            KsPt[(c4 * 4 + 2) * 64 + row] = kv.z;
            KsPt[(c4 * 4 + 3) * 64 + row] = kv.w;
            *(float4*)&Vs[row * 64 + c4 * 4] = *(const float4*)&Vg[row * DH + c4 * 4];
        }
        __syncthreads();

        // S = Q K^T   (pairs along j)
        u64 s2[4][2];
#pragma unroll
        for (int i = 0; i < 4; i++) { s2[i][0] = 0ull; s2[i][1] = 0ull; }
#pragma unroll 8
        for (int h = 0; h < 64; h++) {
            float4 q4 = *(const float4*)&Qs[h * 64 + ty * 4];
            ulonglong2 kp = *(const ulonglong2*)&KsPt[h * 64 + tx * 4];
            u64 p;
            p = pk2(q4.x); fma2(s2[0][0], p, kp.x); fma2(s2[0][1], p, kp.y);
            p = pk2(q4.y); fma2(s2[1][0], p, kp.x); fma2(s2[1][1], p, kp.y);
            p = pk2(q4.z); fma2(s2[2][0], p, kp.x); fma2(s2[2][1], p, kp.y);
            p = pk2(q4.w); fma2(s2[3][0], p, kp.x); fma2(s2[3][1], p, kp.y);
        }

        float s4[4][4];
#pragma unroll
        for (int i = 0; i < 4; i++) {
            float2 lo = up2(s2[i][0]), hi = up2(s2[i][1]);
            s4[i][0] = lo.x; s4[i][1] = lo.y; s4[i][2] = hi.x; s4[i][3] = hi.y;
        }
        if (kt == qt) {
#pragma unroll
            for (int i = 0; i < 4; i++)
#pragma unroll
                for (int j = 0; j < 4; j++)
                    if ((tx * 4 + j) > (ty * 4 + i)) s4[i][j] = -1e30f;
        }

        // online softmax (row stats over tx via shuffles)
#pragma unroll
        for (int i = 0; i < 4; i++) {
            float tmax = fmaxf(fmaxf(s4[i][0], s4[i][1]), fmaxf(s4[i][2], s4[i][3]));
#pragma unroll
            for (int m = 8; m >= 1; m >>= 1)
                tmax = fmaxf(tmax, __shfl_xor_sync(0xffffffffu, tmax, m));
            float mnew  = fmaxf(mrun[i], tmax);
            float alpha = __expf(mrun[i] - mnew);
            float psum  = 0.0f;
#pragma unroll
            for (int j = 0; j < 4; j++) {
                float p = __expf(s4[i][j] - mnew);
                s4[i][j] = p; psum += p;
            }
#pragma unroll
            for (int m = 8; m >= 1; m >>= 1)
                psum += __shfl_xor_sync(0xffffffffu, psum, m);
            lrun[i] = lrun[i] * alpha + psum;
            mrun[i] = mnew;
            u64 pa = pk2(alpha);
            o2[i][0] = mul2(o2[i][0], pa);
            o2[i][1] = mul2(o2[i][1], pa);
        }

        __syncthreads();
#pragma unroll
        for (int j = 0; j < 4; j++)
            *(float4*)&KsPt[(tx * 4 + j) * 64 + ty * 4] =
                make_float4(s4[0][j], s4[1][j], s4[2][j], s4[3][j]);
        __syncthreads();

        // O += P V   (pairs along h)
#pragma unroll 8
        for (int j = 0; j < 64; j++) {
            float4 p4 = *(const float4*)&KsPt[j * 64 + ty * 4];
            ulonglong2 vp = *(const ulonglong2*)&Vs[j * 64 + tx * 4];
            u64 p;
            p = pk2(p4.x); fma2(o2[0][0], p, vp.x); fma2(o2[0][1], p, vp.y);
            p = pk2(p4.y); fma2(o2[1][0], p, vp.x); fma2(o2[1][1], p, vp.y);
            p = pk2(p4.z); fma2(o2[2][0], p, vp.x); fma2(o2[2][1], p, vp.y);
            p = pk2(p4.w); fma2(o2[3][0], p, vp.x); fma2(o2[3][1], p, vp.y);
        }
    }

#pragma unroll
    for (int i = 0; i < 4; i++) {
        float inv = 1.0f / lrun[i];
        float2 lo = up2(o2[i][0]), hi = up2(o2[i][1]);
        float4 r = make_float4(lo.x * inv, lo.y * inv, hi.x * inv, hi.y * inv);
        *(float4*)&g_Oh[((size_t)b * NCTX + q0 + ty * 4 + i) * DH + tx * 4] = r;
    }
}

// ---------------------------------------------------------------------------
// Kernel C: output projection. out[t,d] = sum_h Oh[t,h]*Wo[d,h] + bo[d]
// BM=BN=64, one K pass, FFMA2 pairs along d.
// ---------------------------------------------------------------------------
__global__ __launch_bounds__(256, 1) void proj_kernel(
    const float* __restrict__ Wo, const float* __restrict__ bo,
    float* __restrict__ out)
{
    __shared__ float Ohs[64 * 68];  // [h][t]
    __shared__ float Wos[64 * 68];  // [h][d]

    const int t0  = blockIdx.x * 64;
    const int d0  = blockIdx.y * 64;
    const int tid = threadIdx.x;
    const int tx  = tid & 15;
    const int ty  = tid >> 4;

#pragma unroll
    for (int s = 0; s < 4; s++) {
        int idx = tid + s * 256;
        int row = idx >> 4, c4 = idx & 15;
        float4 v = *(const float4*)&g_Oh[(size_t)(t0 + row) * DH + c4 * 4];
        Ohs[(c4 * 4 + 0) * 68 + row] = v.x; Ohs[(c4 * 4 + 1) * 68 + row] = v.y;
        Ohs[(c4 * 4 + 2) * 68 + row] = v.z; Ohs[(c4 * 4 + 3) * 68 + row] = v.w;
        float4 w = *(const float4*)&Wo[(size_t)(d0 + row) * DH + c4 * 4];
        Wos[(c4 * 4 + 0) * 68 + row] = w.x; Wos[(c4 * 4 + 1) * 68 + row] = w.y;
        Wos[(c4 * 4 + 2) * 68 + row] = w.z; Wos[(c4 * 4 + 3) * 68 + row] = w.w;
    }
    __syncthreads();

    u64 acc2[4][2];
#pragma unroll
    for (int i = 0; i < 4; i++) { acc2[i][0] = 0ull; acc2[i][1] = 0ull; }

#pragma unroll 8
    for (int h = 0; h < 64; h++) {
        float4 o4 = *(const float4*)&Ohs[h * 68 + ty * 4];
        ulonglong2 wp = *(const ulonglong2*)&Wos[h * 68 + tx * 4];
        u64 p;
        p = pk2(o4.x); fma2(acc2[0][0], p, wp.x); fma2(acc2[0][1], p, wp.y);
        p = pk2(o4.y); fma2(acc2[1][0], p, wp.x); fma2(acc2[1][1], p, wp.y);
        p = pk2(o4.z); fma2(acc2[2][0], p, wp.x); fma2(acc2[2][1], p, wp.y);
        p = pk2(o4.w); fma2(acc2[3][0], p, wp.x); fma2(acc2[3][1], p, wp.y);
    }

    float4 b4 = *(const float4*)&bo[d0 + tx * 4];
#pragma unroll
    for (int i = 0; i < 4; i++) {
        float2 lo = up2(acc2[i][0]), hi = up2(acc2[i][1]);
        float4 r = make_float4(lo.x + b4.x, lo.y + b4.y, hi.x + b4.z, hi.y + b4.w);
        *(float4*)&out[(size_t)(t0 + ty * 4 + i) * DM + d0 + tx * 4] = r;
    }
}

// ---------------------------------------------------------------------------
extern "C" void kernel_launch(void* const* d_in, const int* in_sizes, int n_in,
                              void* d_out, int out_size)
{
    const float* x   = (const float*)d_in[0];
    const float* Wq  = (const float*)d_in[1];
    const float* bq  = (const float*)d_in[2];
    const float* Wk  = (const float*)d_in[3];
    const float* bk  = (const float*)d_in[4];
    const float* Wov = (const float*)d_in[5];
    const float* bov = (const float*)d_in[6];
    const float* Wo  = (const float*)d_in[7];
    const float* bo  = (const float*)d_in[8];
    float* out = (float*)d_out;

    qkv_kernel<<<dim3(NT / 128, 3), 256>>>(x, Wq, bq, Wk, bk, Wov, bov);
    attn_kernel<<<256, 256>>>();
    proj_kernel<<<dim3(NT / 64, DM / 64), 256>>>(Wo, bo, out);
}